// round 2
// baseline (speedup 1.0000x reference)
#include <cuda_runtime.h>
#include <cuda_bf16.h>

#define NG 2048      // genes (rows of x)
#define NC 2048      // cells (cols of x)
#define EK 30720     // knn edges (over cells)
#define EP 65536     // ppi edges (over genes)
#define NL 4
#define NN (2048*2048)
#define NEG 0.01f

// ---------------- scratch (static device globals; no allocation) -------------
__device__ float g_T[NN];   // transposed activations
__device__ float g_M[NN];   // aggregation (mean) output
__device__ float g_Z[NN];   // cols-side GEMM out / layer output carrier
__device__ float g_H[NN];   // rows-side activation

__device__ int   g_cnt_knn[NC];
__device__ int   g_off_knn[NC + 1];
__device__ int   g_cur_knn[NC];
__device__ int   g_src_knn[EK];
__device__ float g_inv_knn[NC];

__device__ int   g_cnt_ppi[NG];
__device__ int   g_off_ppi[NG + 1];
__device__ int   g_cur_ppi[NG];
__device__ int   g_src_ppi[EP];
__device__ float g_inv_ppi[NG];

// ---------------- setup kernels ---------------------------------------------
__global__ void zero_counts_kernel() {
    int t = blockIdx.x * blockDim.x + threadIdx.x;
    if (t < NC) g_cnt_knn[t] = 0;
    if (t < NG) g_cnt_ppi[t] = 0;
}

__global__ void count_kernel(const int* __restrict__ tgt, int E, int* __restrict__ cnt) {
    int e = blockIdx.x * blockDim.x + threadIdx.x;
    if (e < E) atomicAdd(&cnt[tgt[e]], 1);
}

// 1 block, 1024 threads, n = 2048: exclusive scan of cnt -> off, plus inv & cursor init
__global__ void scan_kernel(const int* __restrict__ cnt, int* __restrict__ off,
                            float* __restrict__ inv, int* __restrict__ cur, int n) {
    __shared__ int s[1024];
    int t = threadIdx.x;
    int c0 = cnt[2 * t], c1 = cnt[2 * t + 1];
    s[t] = c0 + c1;
    __syncthreads();
    for (int d = 1; d < 1024; d <<= 1) {
        int v = (t >= d) ? s[t - d] : 0;
        __syncthreads();
        s[t] += v;
        __syncthreads();
    }
    int incl = s[t];
    int ex = incl - (c0 + c1);
    off[2 * t] = ex;
    off[2 * t + 1] = ex + c0;
    cur[2 * t] = ex;
    cur[2 * t + 1] = ex + c0;
    inv[2 * t]     = 1.0f / fmaxf((float)c0, 1.0f);
    inv[2 * t + 1] = 1.0f / fmaxf((float)c1, 1.0f);
    if (t == 1023) off[n] = incl;
}

__global__ void fill_kernel(const int* __restrict__ src, const int* __restrict__ tgt,
                            int E, int* __restrict__ cur, int* __restrict__ outsrc) {
    int e = blockIdx.x * blockDim.x + threadIdx.x;
    if (e < E) {
        int p = atomicAdd(&cur[tgt[e]], 1);
        outsrc[p] = src[e];
    }
}

// make per-target source lists deterministic: sort each bucket by value
__global__ void sort_buckets_kernel(const int* __restrict__ off, int* __restrict__ srcs, int n) {
    int t = blockIdx.x * blockDim.x + threadIdx.x;
    if (t >= n) return;
    int a = off[t], b = off[t + 1];
    int m = b - a;
    if (m <= 1 || m > 192) return;
    int buf[192];
    for (int i = 0; i < m; i++) buf[i] = srcs[a + i];
    for (int i = 1; i < m; i++) {
        int key = buf[i];
        int j = i - 1;
        while (j >= 0 && buf[j] > key) { buf[j + 1] = buf[j]; j--; }
        buf[j + 1] = key;
    }
    for (int i = 0; i < m; i++) srcs[a + i] = buf[i];
}

// ---------------- transpose (32x32 tiles) ------------------------------------
__global__ void transpose_kernel(const float* __restrict__ in, float* __restrict__ out) {
    __shared__ float tile[32][33];
    int x = blockIdx.x * 32 + threadIdx.x;
    int y = blockIdx.y * 32 + threadIdx.y;
#pragma unroll
    for (int i = 0; i < 32; i += 8)
        tile[threadIdx.y + i][threadIdx.x] = in[(y + i) * 2048 + x];
    __syncthreads();
    x = blockIdx.y * 32 + threadIdx.x;
    y = blockIdx.x * 32 + threadIdx.y;
#pragma unroll
    for (int i = 0; i < 32; i += 8)
        out[(y + i) * 2048 + x] = tile[threadIdx.x][threadIdx.y + i];
}

// ---------------- segment mean (row gather-sum) ------------------------------
// one block (128 thr) per target row; each thread owns 16 columns as 4 float4s
__global__ void agg_kernel(const float* __restrict__ in, float* __restrict__ out,
                           const int* __restrict__ off, const int* __restrict__ srcs,
                           const float* __restrict__ inv) {
    int r = blockIdx.x;
    int t = threadIdx.x;
    const float4* base = (const float4*)in;
    float4 a0 = make_float4(0.f, 0.f, 0.f, 0.f), a1 = a0, a2 = a0, a3 = a0;
    int s0 = off[r], s1 = off[r + 1];
    for (int j = s0; j < s1; j++) {
        const float4* row = base + (long)srcs[j] * 512;
        float4 v0 = row[t], v1 = row[t + 128], v2 = row[t + 256], v3 = row[t + 384];
        a0.x += v0.x; a0.y += v0.y; a0.z += v0.z; a0.w += v0.w;
        a1.x += v1.x; a1.y += v1.y; a1.z += v1.z; a1.w += v1.w;
        a2.x += v2.x; a2.y += v2.y; a2.z += v2.z; a2.w += v2.w;
        a3.x += v3.x; a3.y += v3.y; a3.z += v3.z; a3.w += v3.w;
    }
    float sc = inv[r];
    a0.x *= sc; a0.y *= sc; a0.z *= sc; a0.w *= sc;
    a1.x *= sc; a1.y *= sc; a1.z *= sc; a1.w *= sc;
    a2.x *= sc; a2.y *= sc; a2.z *= sc; a2.w *= sc;
    a3.x *= sc; a3.y *= sc; a3.z *= sc; a3.w *= sc;
    float4* orow = ((float4*)out) + (long)r * 512;
    orow[t] = a0; orow[t + 128] = a1; orow[t + 256] = a2; orow[t + 384] = a3;
}

// ---------------- fused dual GEMM + bias + LeakyReLU -------------------------
// C[m,n] = sum_k A1[m,k]B1[k,n] + sum_k A2[m,k]B2[k,n] + bias[n], then lrelu
// BM=BN=128, BK=8, 256 threads, 8x8 per thread
__global__ __launch_bounds__(256, 2)
void gemm2_kernel(const float* __restrict__ A1, const float* __restrict__ B1,
                  const float* __restrict__ A2, const float* __restrict__ B2,
                  const float* __restrict__ bias, float* __restrict__ C) {
    __shared__ float As[8][128];
    __shared__ float Bs[8][128];
    int tid = threadIdx.x;
    int tx = tid & 15;       // 0..15 -> n tile
    int ty = tid >> 4;       // 0..15 -> m tile
    int bm = blockIdx.y * 128;
    int bn = blockIdx.x * 128;

    int arow = tid >> 1;           // 0..127
    int acol = (tid & 1) * 4;      // 0 / 4
    int brow = tid >> 5;           // 0..7
    int bcol = (tid & 31) * 4;     // 0..124

    float acc[8][8];
#pragma unroll
    for (int i = 0; i < 8; i++)
#pragma unroll
        for (int j = 0; j < 8; j++) acc[i][j] = 0.f;

    for (int pair = 0; pair < 2; ++pair) {
        const float* A = pair ? A2 : A1;
        const float* B = pair ? B2 : B1;
        for (int t = 0; t < 2048 / 8; ++t) {
            int k0 = t * 8;
            float4 av = *(const float4*)(A + (long)(bm + arow) * 2048 + k0 + acol);
            As[acol + 0][arow] = av.x;
            As[acol + 1][arow] = av.y;
            As[acol + 2][arow] = av.z;
            As[acol + 3][arow] = av.w;
            float4 bv = *(const float4*)(B + (long)(k0 + brow) * 2048 + bn + bcol);
            *(float4*)&Bs[brow][bcol] = bv;
            __syncthreads();
#pragma unroll
            for (int k = 0; k < 8; ++k) {
                float a[8], b[8];
#pragma unroll
                for (int i = 0; i < 8; i++) a[i] = As[k][ty * 8 + i];
#pragma unroll
                for (int j = 0; j < 8; j++) b[j] = Bs[k][tx * 8 + j];
#pragma unroll
                for (int i = 0; i < 8; i++)
#pragma unroll
                    for (int j = 0; j < 8; j++) acc[i][j] += a[i] * b[j];
            }
            __syncthreads();
        }
    }
#pragma unroll
    for (int i = 0; i < 8; i++) {
        int row = bm + ty * 8 + i;
#pragma unroll
        for (int j = 0; j < 8; j++) {
            int col = bn + tx * 8 + j;
            float v = acc[i][j] + bias[col];
            C[(long)row * 2048 + col] = (v > 0.f) ? v : NEG * v;
        }
    }
}

// ---------------- launch -----------------------------------------------------
extern "C" void kernel_launch(void* const* d_in, const int* in_sizes, int n_in,
                              void* d_out, int out_size) {
    const float* x        = (const float*)d_in[0];
    const int*   knn      = (const int*)d_in[1];   // [2, EK]: src row then tgt row
    const int*   ppi      = (const int*)d_in[2];   // [2, EP]
    const float* col_Wl   = (const float*)d_in[3]; // [L, 2048, 2048]
    const float* col_bl   = (const float*)d_in[4]; // [L, 2048]
    const float* col_Wr   = (const float*)d_in[5];
    const float* row_Wl   = (const float*)d_in[6];
    const float* row_bl   = (const float*)d_in[7];
    const float* row_Wr   = (const float*)d_in[8];

    const int* knn_src = knn;
    const int* knn_tgt = knn + EK;
    const int* ppi_src = ppi;
    const int* ppi_tgt = ppi + EP;

    // resolve scratch symbol addresses (no allocation; constant across calls)
    void *pT_, *pM_, *pZ_, *pH_;
    void *pcK, *poK, *puK, *psK, *piK;
    void *pcP, *poP, *puP, *psP, *piP;
    cudaGetSymbolAddress(&pT_, g_T);
    cudaGetSymbolAddress(&pM_, g_M);
    cudaGetSymbolAddress(&pZ_, g_Z);
    cudaGetSymbolAddress(&pH_, g_H);
    cudaGetSymbolAddress(&pcK, g_cnt_knn);
    cudaGetSymbolAddress(&poK, g_off_knn);
    cudaGetSymbolAddress(&puK, g_cur_knn);
    cudaGetSymbolAddress(&psK, g_src_knn);
    cudaGetSymbolAddress(&piK, g_inv_knn);
    cudaGetSymbolAddress(&pcP, g_cnt_ppi);
    cudaGetSymbolAddress(&poP, g_off_ppi);
    cudaGetSymbolAddress(&puP, g_cur_ppi);
    cudaGetSymbolAddress(&psP, g_src_ppi);
    cudaGetSymbolAddress(&piP, g_inv_ppi);

    float* pT = (float*)pT_;
    float* pM = (float*)pM_;
    float* pZ = (float*)pZ_;
    float* pH = (float*)pH_;

    // ---- CSR build (deterministic: buckets sorted by source id) ----
    zero_counts_kernel<<<8, 256>>>();
    count_kernel<<<(EK + 255) / 256, 256>>>(knn_tgt, EK, (int*)pcK);
    count_kernel<<<(EP + 255) / 256, 256>>>(ppi_tgt, EP, (int*)pcP);
    scan_kernel<<<1, 1024>>>((int*)pcK, (int*)poK, (float*)piK, (int*)puK, NC);
    scan_kernel<<<1, 1024>>>((int*)pcP, (int*)poP, (float*)piP, (int*)puP, NG);
    fill_kernel<<<(EK + 255) / 256, 256>>>(knn_src, knn_tgt, EK, (int*)puK, (int*)psK);
    fill_kernel<<<(EP + 255) / 256, 256>>>(ppi_src, ppi_tgt, EP, (int*)puP, (int*)psP);
    sort_buckets_kernel<<<8, 256>>>((int*)poK, (int*)psK, NC);
    sort_buckets_kernel<<<8, 256>>>((int*)poP, (int*)psP, NG);

    dim3 tgrid(64, 64), tblk(32, 8);
    dim3 ggrid(16, 16);

    const float* h = x;
    for (int i = 0; i < NL; ++i) {
        const float* cWl = col_Wl + (long)i * NN;
        const float* cWr = col_Wr + (long)i * NN;
        const float* cbl = col_bl + (long)i * 2048;
        const float* rWl = row_Wl + (long)i * NN;
        const float* rWr = row_Wr + (long)i * NN;
        const float* rbl = row_bl + (long)i * 2048;

        // cols side: hT over KNN graph
        transpose_kernel<<<tgrid, tblk>>>(h, pT);
        agg_kernel<<<NC, 128>>>(pT, pM, (int*)poK, (int*)psK, (float*)piK);
        gemm2_kernel<<<ggrid, 256>>>(pM, cWl, pT, cWr, cbl, pZ);

        // rows side: back to [genes, cells] over PPI graph
        transpose_kernel<<<tgrid, tblk>>>(pZ, pH);
        agg_kernel<<<NG, 128>>>(pH, pM, (int*)poP, (int*)psP, (float*)piP);
        float* dst = (i == NL - 1) ? (float*)d_out : pZ;
        gemm2_kernel<<<ggrid, 256>>>(pM, rWl, pH, rWr, rbl, dst);
        h = dst;
    }
}

// round 3
// speedup vs baseline: 1.0005x; 1.0005x over previous
#include <cuda_runtime.h>
#include <cuda_bf16.h>

#define NG 2048      // genes (rows of x)
#define NC 2048      // cells (cols of x)
#define EK 30720     // knn edges (over cells)
#define EP 65536     // ppi edges (over genes)
#define NL 4
#define NN (2048*2048)
#define NEG 0.01f

// ---------------- scratch (static device globals; no allocation) -------------
__device__ float g_T[NN];   // transposed activations
__device__ float g_M[NN];   // aggregation (mean) output
__device__ float g_Z[NN];   // cols-side GEMM out / layer output carrier
__device__ float g_H[NN];   // rows-side activation

__device__ int   g_cnt_knn[NC];
__device__ int   g_off_knn[NC + 1];
__device__ int   g_cur_knn[NC];
__device__ int   g_src_knn[EK];
__device__ float g_inv_knn[NC];

__device__ int   g_cnt_ppi[NG];
__device__ int   g_off_ppi[NG + 1];
__device__ int   g_cur_ppi[NG];
__device__ int   g_src_ppi[EP];
__device__ float g_inv_ppi[NG];

// ---------------- setup kernels ---------------------------------------------
__global__ void zero_counts_kernel() {
    int t = blockIdx.x * blockDim.x + threadIdx.x;
    if (t < NC) g_cnt_knn[t] = 0;
    if (t < NG) g_cnt_ppi[t] = 0;
}

__global__ void count_kernel(const int* __restrict__ tgt, int E, int* __restrict__ cnt) {
    int e = blockIdx.x * blockDim.x + threadIdx.x;
    if (e < E) atomicAdd(&cnt[tgt[e]], 1);
}

// 1 block, 1024 threads, n = 2048: exclusive scan of cnt -> off, plus inv & cursor init
__global__ void scan_kernel(const int* __restrict__ cnt, int* __restrict__ off,
                            float* __restrict__ inv, int* __restrict__ cur, int n) {
    __shared__ int s[1024];
    int t = threadIdx.x;
    int c0 = cnt[2 * t], c1 = cnt[2 * t + 1];
    s[t] = c0 + c1;
    __syncthreads();
    for (int d = 1; d < 1024; d <<= 1) {
        int v = (t >= d) ? s[t - d] : 0;
        __syncthreads();
        s[t] += v;
        __syncthreads();
    }
    int incl = s[t];
    int ex = incl - (c0 + c1);
    off[2 * t] = ex;
    off[2 * t + 1] = ex + c0;
    cur[2 * t] = ex;
    cur[2 * t + 1] = ex + c0;
    inv[2 * t]     = 1.0f / fmaxf((float)c0, 1.0f);
    inv[2 * t + 1] = 1.0f / fmaxf((float)c1, 1.0f);
    if (t == 1023) off[n] = incl;
}

__global__ void fill_kernel(const int* __restrict__ src, const int* __restrict__ tgt,
                            int E, int* __restrict__ cur, int* __restrict__ outsrc) {
    int e = blockIdx.x * blockDim.x + threadIdx.x;
    if (e < E) {
        int p = atomicAdd(&cur[tgt[e]], 1);
        outsrc[p] = src[e];
    }
}

// make per-target source lists deterministic: sort each bucket by value
__global__ void sort_buckets_kernel(const int* __restrict__ off, int* __restrict__ srcs, int n) {
    int t = blockIdx.x * blockDim.x + threadIdx.x;
    if (t >= n) return;
    int a = off[t], b = off[t + 1];
    int m = b - a;
    if (m <= 1 || m > 192) return;
    int buf[192];
    for (int i = 0; i < m; i++) buf[i] = srcs[a + i];
    for (int i = 1; i < m; i++) {
        int key = buf[i];
        int j = i - 1;
        while (j >= 0 && buf[j] > key) { buf[j + 1] = buf[j]; j--; }
        buf[j + 1] = key;
    }
    for (int i = 0; i < m; i++) srcs[a + i] = buf[i];
}

// ---------------- transpose (32x32 tiles) ------------------------------------
__global__ void transpose_kernel(const float* __restrict__ in, float* __restrict__ out) {
    __shared__ float tile[32][33];
    int x = blockIdx.x * 32 + threadIdx.x;
    int y = blockIdx.y * 32 + threadIdx.y;
#pragma unroll
    for (int i = 0; i < 32; i += 8)
        tile[threadIdx.y + i][threadIdx.x] = in[(y + i) * 2048 + x];
    __syncthreads();
    x = blockIdx.y * 32 + threadIdx.x;
    y = blockIdx.x * 32 + threadIdx.y;
#pragma unroll
    for (int i = 0; i < 32; i += 8)
        out[(y + i) * 2048 + x] = tile[threadIdx.x][threadIdx.y + i];
}

// ---------------- segment mean (row gather-sum) ------------------------------
// one block (128 thr) per target row; each thread owns 16 columns as 4 float4s
__global__ void agg_kernel(const float* __restrict__ in, float* __restrict__ out,
                           const int* __restrict__ off, const int* __restrict__ srcs,
                           const float* __restrict__ inv) {
    int r = blockIdx.x;
    int t = threadIdx.x;
    const float4* base = (const float4*)in;
    float4 a0 = make_float4(0.f, 0.f, 0.f, 0.f), a1 = a0, a2 = a0, a3 = a0;
    int s0 = off[r], s1 = off[r + 1];
    for (int j = s0; j < s1; j++) {
        const float4* row = base + (long)srcs[j] * 512;
        float4 v0 = row[t], v1 = row[t + 128], v2 = row[t + 256], v3 = row[t + 384];
        a0.x += v0.x; a0.y += v0.y; a0.z += v0.z; a0.w += v0.w;
        a1.x += v1.x; a1.y += v1.y; a1.z += v1.z; a1.w += v1.w;
        a2.x += v2.x; a2.y += v2.y; a2.z += v2.z; a2.w += v2.w;
        a3.x += v3.x; a3.y += v3.y; a3.z += v3.z; a3.w += v3.w;
    }
    float sc = inv[r];
    a0.x *= sc; a0.y *= sc; a0.z *= sc; a0.w *= sc;
    a1.x *= sc; a1.y *= sc; a1.z *= sc; a1.w *= sc;
    a2.x *= sc; a2.y *= sc; a2.z *= sc; a2.w *= sc;
    a3.x *= sc; a3.y *= sc; a3.z *= sc; a3.w *= sc;
    float4* orow = ((float4*)out) + (long)r * 512;
    orow[t] = a0; orow[t + 128] = a1; orow[t + 256] = a2; orow[t + 384] = a3;
}

// ---------------- fused dual GEMM + bias + LeakyReLU -------------------------
// C[m,n] = sum_k A1[m,k]B1[k,n] + sum_k A2[m,k]B2[k,n] + bias[n], then lrelu
// BM=BN=128, BK=8, 256 threads, 8x8 per thread
__global__ __launch_bounds__(256, 2)
void gemm2_kernel(const float* __restrict__ A1, const float* __restrict__ B1,
                  const float* __restrict__ A2, const float* __restrict__ B2,
                  const float* __restrict__ bias, float* __restrict__ C) {
    __shared__ float As[8][128];
    __shared__ float Bs[8][128];
    int tid = threadIdx.x;
    int tx = tid & 15;       // 0..15 -> n tile
    int ty = tid >> 4;       // 0..15 -> m tile
    int bm = blockIdx.y * 128;
    int bn = blockIdx.x * 128;

    int arow = tid >> 1;           // 0..127
    int acol = (tid & 1) * 4;      // 0 / 4
    int brow = tid >> 5;           // 0..7
    int bcol = (tid & 31) * 4;     // 0..124

    float acc[8][8];
#pragma unroll
    for (int i = 0; i < 8; i++)
#pragma unroll
        for (int j = 0; j < 8; j++) acc[i][j] = 0.f;

    for (int pair = 0; pair < 2; ++pair) {
        const float* A = pair ? A2 : A1;
        const float* B = pair ? B2 : B1;
        for (int t = 0; t < 2048 / 8; ++t) {
            int k0 = t * 8;
            float4 av = *(const float4*)(A + (long)(bm + arow) * 2048 + k0 + acol);
            As[acol + 0][arow] = av.x;
            As[acol + 1][arow] = av.y;
            As[acol + 2][arow] = av.z;
            As[acol + 3][arow] = av.w;
            float4 bv = *(const float4*)(B + (long)(k0 + brow) * 2048 + bn + bcol);
            *(float4*)&Bs[brow][bcol] = bv;
            __syncthreads();
#pragma unroll
            for (int k = 0; k < 8; ++k) {
                float a[8], b[8];
#pragma unroll
                for (int i = 0; i < 8; i++) a[i] = As[k][ty * 8 + i];
#pragma unroll
                for (int j = 0; j < 8; j++) b[j] = Bs[k][tx * 8 + j];
#pragma unroll
                for (int i = 0; i < 8; i++)
#pragma unroll
                    for (int j = 0; j < 8; j++) acc[i][j] += a[i] * b[j];
            }
            __syncthreads();
        }
    }
#pragma unroll
    for (int i = 0; i < 8; i++) {
        int row = bm + ty * 8 + i;
#pragma unroll
        for (int j = 0; j < 8; j++) {
            int col = bn + tx * 8 + j;
            float v = acc[i][j] + bias[col];
            C[(long)row * 2048 + col] = (v > 0.f) ? v : NEG * v;
        }
    }
}

// ---------------- launch -----------------------------------------------------
extern "C" void kernel_launch(void* const* d_in, const int* in_sizes, int n_in,
                              void* d_out, int out_size) {
    const float* x        = (const float*)d_in[0];
    const int*   knn      = (const int*)d_in[1];   // [2, EK]: src row then tgt row
    const int*   ppi      = (const int*)d_in[2];   // [2, EP]
    const float* col_Wl   = (const float*)d_in[3]; // [L, 2048, 2048]
    const float* col_bl   = (const float*)d_in[4]; // [L, 2048]
    const float* col_Wr   = (const float*)d_in[5];
    const float* row_Wl   = (const float*)d_in[6];
    const float* row_bl   = (const float*)d_in[7];
    const float* row_Wr   = (const float*)d_in[8];

    const int* knn_src = knn;
    const int* knn_tgt = knn + EK;
    const int* ppi_src = ppi;
    const int* ppi_tgt = ppi + EP;

    // resolve scratch symbol addresses (no allocation; constant across calls)
    void *pT_, *pM_, *pZ_, *pH_;
    void *pcK, *poK, *puK, *psK, *piK;
    void *pcP, *poP, *puP, *psP, *piP;
    cudaGetSymbolAddress(&pT_, g_T);
    cudaGetSymbolAddress(&pM_, g_M);
    cudaGetSymbolAddress(&pZ_, g_Z);
    cudaGetSymbolAddress(&pH_, g_H);
    cudaGetSymbolAddress(&pcK, g_cnt_knn);
    cudaGetSymbolAddress(&poK, g_off_knn);
    cudaGetSymbolAddress(&puK, g_cur_knn);
    cudaGetSymbolAddress(&psK, g_src_knn);
    cudaGetSymbolAddress(&piK, g_inv_knn);
    cudaGetSymbolAddress(&pcP, g_cnt_ppi);
    cudaGetSymbolAddress(&poP, g_off_ppi);
    cudaGetSymbolAddress(&puP, g_cur_ppi);
    cudaGetSymbolAddress(&psP, g_src_ppi);
    cudaGetSymbolAddress(&piP, g_inv_ppi);

    float* pT = (float*)pT_;
    float* pM = (float*)pM_;
    float* pZ = (float*)pZ_;
    float* pH = (float*)pH_;

    // ---- CSR build (deterministic: buckets sorted by source id) ----
    zero_counts_kernel<<<8, 256>>>();
    count_kernel<<<(EK + 255) / 256, 256>>>(knn_tgt, EK, (int*)pcK);
    count_kernel<<<(EP + 255) / 256, 256>>>(ppi_tgt, EP, (int*)pcP);
    scan_kernel<<<1, 1024>>>((int*)pcK, (int*)poK, (float*)piK, (int*)puK, NC);
    scan_kernel<<<1, 1024>>>((int*)pcP, (int*)poP, (float*)piP, (int*)puP, NG);
    fill_kernel<<<(EK + 255) / 256, 256>>>(knn_src, knn_tgt, EK, (int*)puK, (int*)psK);
    fill_kernel<<<(EP + 255) / 256, 256>>>(ppi_src, ppi_tgt, EP, (int*)puP, (int*)psP);
    sort_buckets_kernel<<<8, 256>>>((int*)poK, (int*)psK, NC);
    sort_buckets_kernel<<<8, 256>>>((int*)poP, (int*)psP, NG);

    dim3 tgrid(64, 64), tblk(32, 8);
    dim3 ggrid(16, 16);

    const float* h = x;
    for (int i = 0; i < NL; ++i) {
        const float* cWl = col_Wl + (long)i * NN;
        const float* cWr = col_Wr + (long)i * NN;
        const float* cbl = col_bl + (long)i * 2048;
        const float* rWl = row_Wl + (long)i * NN;
        const float* rWr = row_Wr + (long)i * NN;
        const float* rbl = row_bl + (long)i * 2048;

        // cols side: hT over KNN graph
        transpose_kernel<<<tgrid, tblk>>>(h, pT);
        agg_kernel<<<NC, 128>>>(pT, pM, (int*)poK, (int*)psK, (float*)piK);
        gemm2_kernel<<<ggrid, 256>>>(pM, cWl, pT, cWr, cbl, pZ);

        // rows side: back to [genes, cells] over PPI graph
        transpose_kernel<<<tgrid, tblk>>>(pZ, pH);
        agg_kernel<<<NG, 128>>>(pH, pM, (int*)poP, (int*)psP, (float*)piP);
        float* dst = (i == NL - 1) ? (float*)d_out : pZ;
        gemm2_kernel<<<ggrid, 256>>>(pM, rWl, pH, rWr, rbl, dst);
        h = dst;
    }
}

// round 4
// speedup vs baseline: 1.0006x; 1.0001x over previous
#include <cuda_runtime.h>
#include <cuda_bf16.h>

#define NG 2048      // genes (rows of x)
#define NC 2048      // cells (cols of x)
#define EK 30720     // knn edges (over cells)
#define EP 65536     // ppi edges (over genes)
#define NL 4
#define NN (2048*2048)
#define NEG 0.01f

// ---------------- scratch (static device globals; no allocation) -------------
__device__ float g_T[NN];   // transposed activations
__device__ float g_M[NN];   // aggregation (mean) output
__device__ float g_Z[NN];   // cols-side GEMM out / layer output carrier
__device__ float g_H[NN];   // rows-side activation

__device__ int   g_cnt_knn[NC];
__device__ int   g_off_knn[NC + 1];
__device__ int   g_cur_knn[NC];
__device__ int   g_src_knn[EK];
__device__ float g_inv_knn[NC];

__device__ int   g_cnt_ppi[NG];
__device__ int   g_off_ppi[NG + 1];
__device__ int   g_cur_ppi[NG];
__device__ int   g_src_ppi[EP];
__device__ float g_inv_ppi[NG];

// ---------------- setup kernels ---------------------------------------------
__global__ void zero_counts_kernel() {
    int t = blockIdx.x * blockDim.x + threadIdx.x;
    if (t < NC) g_cnt_knn[t] = 0;
    if (t < NG) g_cnt_ppi[t] = 0;
}

__global__ void count_kernel(const int* __restrict__ tgt, int E, int* __restrict__ cnt) {
    int e = blockIdx.x * blockDim.x + threadIdx.x;
    if (e < E) atomicAdd(&cnt[tgt[e]], 1);
}

// 1 block, 1024 threads, n = 2048: exclusive scan of cnt -> off, plus inv & cursor init
__global__ void scan_kernel(const int* __restrict__ cnt, int* __restrict__ off,
                            float* __restrict__ inv, int* __restrict__ cur, int n) {
    __shared__ int s[1024];
    int t = threadIdx.x;
    int c0 = cnt[2 * t], c1 = cnt[2 * t + 1];
    s[t] = c0 + c1;
    __syncthreads();
    for (int d = 1; d < 1024; d <<= 1) {
        int v = (t >= d) ? s[t - d] : 0;
        __syncthreads();
        s[t] += v;
        __syncthreads();
    }
    int incl = s[t];
    int ex = incl - (c0 + c1);
    off[2 * t] = ex;
    off[2 * t + 1] = ex + c0;
    cur[2 * t] = ex;
    cur[2 * t + 1] = ex + c0;
    inv[2 * t]     = 1.0f / fmaxf((float)c0, 1.0f);
    inv[2 * t + 1] = 1.0f / fmaxf((float)c1, 1.0f);
    if (t == 1023) off[n] = incl;
}

__global__ void fill_kernel(const int* __restrict__ src, const int* __restrict__ tgt,
                            int E, int* __restrict__ cur, int* __restrict__ outsrc) {
    int e = blockIdx.x * blockDim.x + threadIdx.x;
    if (e < E) {
        int p = atomicAdd(&cur[tgt[e]], 1);
        outsrc[p] = src[e];
    }
}

// make per-target source lists deterministic: sort each bucket by value
__global__ void sort_buckets_kernel(const int* __restrict__ off, int* __restrict__ srcs, int n) {
    int t = blockIdx.x * blockDim.x + threadIdx.x;
    if (t >= n) return;
    int a = off[t], b = off[t + 1];
    int m = b - a;
    if (m <= 1 || m > 192) return;
    int buf[192];
    for (int i = 0; i < m; i++) buf[i] = srcs[a + i];
    for (int i = 1; i < m; i++) {
        int key = buf[i];
        int j = i - 1;
        while (j >= 0 && buf[j] > key) { buf[j + 1] = buf[j]; j--; }
        buf[j + 1] = key;
    }
    for (int i = 0; i < m; i++) srcs[a + i] = buf[i];
}

// ---------------- transpose (32x32 tiles) ------------------------------------
__global__ void transpose_kernel(const float* __restrict__ in, float* __restrict__ out) {
    __shared__ float tile[32][33];
    int x = blockIdx.x * 32 + threadIdx.x;
    int y = blockIdx.y * 32 + threadIdx.y;
#pragma unroll
    for (int i = 0; i < 32; i += 8)
        tile[threadIdx.y + i][threadIdx.x] = in[(y + i) * 2048 + x];
    __syncthreads();
    x = blockIdx.y * 32 + threadIdx.x;
    y = blockIdx.x * 32 + threadIdx.y;
#pragma unroll
    for (int i = 0; i < 32; i += 8)
        out[(y + i) * 2048 + x] = tile[threadIdx.x][threadIdx.y + i];
}

// ---------------- segment mean (row gather-sum) ------------------------------
// one block (128 thr) per target row; each thread owns 16 columns as 4 float4s
__global__ void agg_kernel(const float* __restrict__ in, float* __restrict__ out,
                           const int* __restrict__ off, const int* __restrict__ srcs,
                           const float* __restrict__ inv) {
    int r = blockIdx.x;
    int t = threadIdx.x;
    const float4* base = (const float4*)in;
    float4 a0 = make_float4(0.f, 0.f, 0.f, 0.f), a1 = a0, a2 = a0, a3 = a0;
    int s0 = off[r], s1 = off[r + 1];
    for (int j = s0; j < s1; j++) {
        const float4* row = base + (long)srcs[j] * 512;
        float4 v0 = row[t], v1 = row[t + 128], v2 = row[t + 256], v3 = row[t + 384];
        a0.x += v0.x; a0.y += v0.y; a0.z += v0.z; a0.w += v0.w;
        a1.x += v1.x; a1.y += v1.y; a1.z += v1.z; a1.w += v1.w;
        a2.x += v2.x; a2.y += v2.y; a2.z += v2.z; a2.w += v2.w;
        a3.x += v3.x; a3.y += v3.y; a3.z += v3.z; a3.w += v3.w;
    }
    float sc = inv[r];
    a0.x *= sc; a0.y *= sc; a0.z *= sc; a0.w *= sc;
    a1.x *= sc; a1.y *= sc; a1.z *= sc; a1.w *= sc;
    a2.x *= sc; a2.y *= sc; a2.z *= sc; a2.w *= sc;
    a3.x *= sc; a3.y *= sc; a3.z *= sc; a3.w *= sc;
    float4* orow = ((float4*)out) + (long)r * 512;
    orow[t] = a0; orow[t + 128] = a1; orow[t + 256] = a2; orow[t + 384] = a3;
}

// ---------------- fused dual GEMM + bias + LeakyReLU -------------------------
// C[m,n] = sum_k A1[m,k]B1[k,n] + sum_k A2[m,k]B2[k,n] + bias[n], then lrelu
// BM=BN=128, BK=8, 256 threads, 8x8 per thread
__global__ __launch_bounds__(256, 2)
void gemm2_kernel(const float* __restrict__ A1, const float* __restrict__ B1,
                  const float* __restrict__ A2, const float* __restrict__ B2,
                  const float* __restrict__ bias, float* __restrict__ C) {
    __shared__ float As[8][128];
    __shared__ float Bs[8][128];
    int tid = threadIdx.x;
    int tx = tid & 15;       // 0..15 -> n tile
    int ty = tid >> 4;       // 0..15 -> m tile
    int bm = blockIdx.y * 128;
    int bn = blockIdx.x * 128;

    int arow = tid >> 1;           // 0..127
    int acol = (tid & 1) * 4;      // 0 / 4
    int brow = tid >> 5;           // 0..7
    int bcol = (tid & 31) * 4;     // 0..124

    float acc[8][8];
#pragma unroll
    for (int i = 0; i < 8; i++)
#pragma unroll
        for (int j = 0; j < 8; j++) acc[i][j] = 0.f;

    for (int pair = 0; pair < 2; ++pair) {
        const float* A = pair ? A2 : A1;
        const float* B = pair ? B2 : B1;
        for (int t = 0; t < 2048 / 8; ++t) {
            int k0 = t * 8;
            float4 av = *(const float4*)(A + (long)(bm + arow) * 2048 + k0 + acol);
            As[acol + 0][arow] = av.x;
            As[acol + 1][arow] = av.y;
            As[acol + 2][arow] = av.z;
            As[acol + 3][arow] = av.w;
            float4 bv = *(const float4*)(B + (long)(k0 + brow) * 2048 + bn + bcol);
            *(float4*)&Bs[brow][bcol] = bv;
            __syncthreads();
#pragma unroll
            for (int k = 0; k < 8; ++k) {
                float a[8], b[8];
#pragma unroll
                for (int i = 0; i < 8; i++) a[i] = As[k][ty * 8 + i];
#pragma unroll
                for (int j = 0; j < 8; j++) b[j] = Bs[k][tx * 8 + j];
#pragma unroll
                for (int i = 0; i < 8; i++)
#pragma unroll
                    for (int j = 0; j < 8; j++) acc[i][j] += a[i] * b[j];
            }
            __syncthreads();
        }
    }
#pragma unroll
    for (int i = 0; i < 8; i++) {
        int row = bm + ty * 8 + i;
#pragma unroll
        for (int j = 0; j < 8; j++) {
            int col = bn + tx * 8 + j;
            float v = acc[i][j] + bias[col];
            C[(long)row * 2048 + col] = (v > 0.f) ? v : NEG * v;
        }
    }
}

// ---------------- launch -----------------------------------------------------
extern "C" void kernel_launch(void* const* d_in, const int* in_sizes, int n_in,
                              void* d_out, int out_size) {
    const float* x        = (const float*)d_in[0];
    const int*   knn      = (const int*)d_in[1];   // [2, EK]: src row then tgt row
    const int*   ppi      = (const int*)d_in[2];   // [2, EP]
    const float* col_Wl   = (const float*)d_in[3]; // [L, 2048, 2048]
    const float* col_bl   = (const float*)d_in[4]; // [L, 2048]
    const float* col_Wr   = (const float*)d_in[5];
    const float* row_Wl   = (const float*)d_in[6];
    const float* row_bl   = (const float*)d_in[7];
    const float* row_Wr   = (const float*)d_in[8];

    const int* knn_src = knn;
    const int* knn_tgt = knn + EK;
    const int* ppi_src = ppi;
    const int* ppi_tgt = ppi + EP;

    // resolve scratch symbol addresses (no allocation; constant across calls)
    void *pT_, *pM_, *pZ_, *pH_;
    void *pcK, *poK, *puK, *psK, *piK;
    void *pcP, *poP, *puP, *psP, *piP;
    cudaGetSymbolAddress(&pT_, g_T);
    cudaGetSymbolAddress(&pM_, g_M);
    cudaGetSymbolAddress(&pZ_, g_Z);
    cudaGetSymbolAddress(&pH_, g_H);
    cudaGetSymbolAddress(&pcK, g_cnt_knn);
    cudaGetSymbolAddress(&poK, g_off_knn);
    cudaGetSymbolAddress(&puK, g_cur_knn);
    cudaGetSymbolAddress(&psK, g_src_knn);
    cudaGetSymbolAddress(&piK, g_inv_knn);
    cudaGetSymbolAddress(&pcP, g_cnt_ppi);
    cudaGetSymbolAddress(&poP, g_off_ppi);
    cudaGetSymbolAddress(&puP, g_cur_ppi);
    cudaGetSymbolAddress(&psP, g_src_ppi);
    cudaGetSymbolAddress(&piP, g_inv_ppi);

    float* pT = (float*)pT_;
    float* pM = (float*)pM_;
    float* pZ = (float*)pZ_;
    float* pH = (float*)pH_;

    // ---- CSR build (deterministic: buckets sorted by source id) ----
    zero_counts_kernel<<<8, 256>>>();
    count_kernel<<<(EK + 255) / 256, 256>>>(knn_tgt, EK, (int*)pcK);
    count_kernel<<<(EP + 255) / 256, 256>>>(ppi_tgt, EP, (int*)pcP);
    scan_kernel<<<1, 1024>>>((int*)pcK, (int*)poK, (float*)piK, (int*)puK, NC);
    scan_kernel<<<1, 1024>>>((int*)pcP, (int*)poP, (float*)piP, (int*)puP, NG);
    fill_kernel<<<(EK + 255) / 256, 256>>>(knn_src, knn_tgt, EK, (int*)puK, (int*)psK);
    fill_kernel<<<(EP + 255) / 256, 256>>>(ppi_src, ppi_tgt, EP, (int*)puP, (int*)psP);
    sort_buckets_kernel<<<8, 256>>>((int*)poK, (int*)psK, NC);
    sort_buckets_kernel<<<8, 256>>>((int*)poP, (int*)psP, NG);

    dim3 tgrid(64, 64), tblk(32, 8);
    dim3 ggrid(16, 16);

    const float* h = x;
    for (int i = 0; i < NL; ++i) {
        const float* cWl = col_Wl + (long)i * NN;
        const float* cWr = col_Wr + (long)i * NN;
        const float* cbl = col_bl + (long)i * 2048;
        const float* rWl = row_Wl + (long)i * NN;
        const float* rWr = row_Wr + (long)i * NN;
        const float* rbl = row_bl + (long)i * 2048;

        // cols side: hT over KNN graph
        transpose_kernel<<<tgrid, tblk>>>(h, pT);
        agg_kernel<<<NC, 128>>>(pT, pM, (int*)poK, (int*)psK, (float*)piK);
        gemm2_kernel<<<ggrid, 256>>>(pM, cWl, pT, cWr, cbl, pZ);

        // rows side: back to [genes, cells] over PPI graph
        transpose_kernel<<<tgrid, tblk>>>(pZ, pH);
        agg_kernel<<<NG, 128>>>(pH, pM, (int*)poP, (int*)psP, (float*)piP);
        float* dst = (i == NL - 1) ? (float*)d_out : pZ;
        gemm2_kernel<<<ggrid, 256>>>(pM, rWl, pH, rWr, rbl, dst);
        h = dst;
    }
}